// round 1
// baseline (speedup 1.0000x reference)
#include <cuda_runtime.h>

#define NTOK 50
#define DDIM 64
#define FP   68   // pitch for sF, sH (mult of 4 for float4 rows; banks (4n+d) for column reads)
#define QP   65   // pitch for sQ (scalar column reads, <=2-way conflicts)

// smem layout (floats):
//   sF [50][68]  = 3400
//   sK [64][64]  = 4096   (K_w row-major as-is)
//   sQ [64][65]  = 4160   (Q_w row-major, padded)
//   sG [64][64]  = 4096   (G = F^T F)
//   sH [50][68]  = 3400   (H = F @ K_w)
#define SMEM_FLOATS (NTOK*FP + 64*64 + 64*QP + 64*64 + NTOK*FP)

__global__ __launch_bounds__(256, 2)
void SAM3E_kernel(const float* __restrict__ Fg,
                  const float* __restrict__ Kw,
                  const float* __restrict__ Qw,
                  float* __restrict__ outg)
{
    extern __shared__ float sm[];
    float* sF = sm;
    float* sK = sF + NTOK * FP;
    float* sQ = sK + 64 * 64;
    float* sG = sQ + 64 * QP;
    float* sH = sG + 64 * 64;

    const int b   = blockIdx.x;
    const int tid = threadIdx.x;
    const float* Fb = Fg + (size_t)b * (NTOK * DDIM);

    // ---- stage inputs into smem (coalesced reads, conflict-free writes) ----
    for (int idx = tid; idx < NTOK * DDIM; idx += 256) {
        int n = idx >> 6, d = idx & 63;
        sF[n * FP + d] = Fb[idx];
    }
    for (int idx = tid; idx < 64 * 64; idx += 256) {
        sK[idx] = Kw[idx];                       // sK[d][e] = K_w[d][e]
    }
    for (int idx = tid; idx < 64 * 64; idx += 256) {
        int e = idx >> 6, d = idx & 63;
        sQ[e * QP + d] = Qw[idx];                // sQ[e][d] = Q_w[e][d]
    }
    __syncthreads();

    // ---- Phase 1: G = F^T F.  256 threads as 16x16, each a 4x4 tile ----
    {
        const int i = tid >> 4, j = tid & 15;
        float acc[4][4] = {};
        const float* fa = sF + 4 * i;
        const float* fb = sF + 4 * j;
        #pragma unroll 5
        for (int n = 0; n < NTOK; ++n) {
            float4 a4 = *(const float4*)(fa + n * FP);
            float4 b4 = *(const float4*)(fb + n * FP);
            float av[4] = {a4.x, a4.y, a4.z, a4.w};
            float bv[4] = {b4.x, b4.y, b4.z, b4.w};
            #pragma unroll
            for (int p = 0; p < 4; ++p)
                #pragma unroll
                for (int q = 0; q < 4; ++q)
                    acc[p][q] += av[p] * bv[q];
        }
        #pragma unroll
        for (int p = 0; p < 4; ++p)
            *(float4*)(sG + (4 * i + p) * 64 + 4 * j) =
                make_float4(acc[p][0], acc[p][1], acc[p][2], acc[p][3]);
    }
    // NOTE: phase 2 reads only sF/sK/sQ (synced above) and writes sH;
    // phase 1 writes sG. No hazard between them -> no extra sync here.

    // ---- Phase 2: H = F@K_w (to smem) and QF = F@Q_w^T (to regs) ----
    // 208 active threads: r = tid/16 in [0,13), c = tid%16. Tile rows 4r..4r+3, cols 4c..4c+3.
    const bool act = tid < 208;
    const int r  = tid >> 4;
    const int c  = tid & 15;
    const int n0 = 4 * r;
    const int e0 = 4 * c;

    int nr[4];
    #pragma unroll
    for (int a = 0; a < 4; ++a) {
        int n = n0 + a;
        nr[a] = (n < NTOK) ? n : (NTOK - 1);   // clamp loads; stores guarded
    }

    float qf[4][4] = {};
    if (act) {
        float h[4][4] = {};
        #pragma unroll 4
        for (int d = 0; d < 64; ++d) {
            float fv[4];
            #pragma unroll
            for (int a = 0; a < 4; ++a) fv[a] = sF[nr[a] * FP + d];
            float4 k4 = *(const float4*)(sK + d * 64 + e0);
            float kv[4] = {k4.x, k4.y, k4.z, k4.w};
            float qv[4];
            #pragma unroll
            for (int k = 0; k < 4; ++k) qv[k] = sQ[(e0 + k) * QP + d];
            #pragma unroll
            for (int a = 0; a < 4; ++a)
                #pragma unroll
                for (int k = 0; k < 4; ++k) {
                    h[a][k]  += fv[a] * kv[k];
                    qf[a][k] += fv[a] * qv[k];
                }
        }
        #pragma unroll
        for (int a = 0; a < 4; ++a)
            if (n0 + a < NTOK)
                *(float4*)(sH + (n0 + a) * FP + e0) =
                    make_float4(h[a][0], h[a][1], h[a][2], h[a][3]);
    }
    __syncthreads();   // sG (phase1) and sH (phase2) now visible

    // ---- Phase 3: T = H @ G, then out = F .* T + QF ----
    if (act) {
        float t[4][4] = {};
        #pragma unroll 4
        for (int e = 0; e < 64; ++e) {
            float hv[4];
            #pragma unroll
            for (int a = 0; a < 4; ++a) hv[a] = sH[nr[a] * FP + e];
            float4 g4 = *(const float4*)(sG + e * 64 + e0);
            float gv[4] = {g4.x, g4.y, g4.z, g4.w};
            #pragma unroll
            for (int a = 0; a < 4; ++a)
                #pragma unroll
                for (int k = 0; k < 4; ++k)
                    t[a][k] += hv[a] * gv[k];
        }
        float* ob = outg + (size_t)b * (NTOK * DDIM);
        #pragma unroll
        for (int a = 0; a < 4; ++a) {
            int n = n0 + a;
            if (n < NTOK) {
                float4 f4 = *(const float4*)(sF + n * FP + e0);
                float4 o;
                o.x = f4.x * t[a][0] + qf[a][0];
                o.y = f4.y * t[a][1] + qf[a][1];
                o.z = f4.z * t[a][2] + qf[a][2];
                o.w = f4.w * t[a][3] + qf[a][3];
                *(float4*)(ob + n * 64 + e0) = o;
            }
        }
    }
}

extern "C" void kernel_launch(void* const* d_in, const int* in_sizes, int n_in,
                              void* d_out, int out_size)
{
    const float* F  = (const float*)d_in[0];
    const float* Kw = (const float*)d_in[1];
    const float* Qw = (const float*)d_in[2];
    float* out      = (float*)d_out;

    const int B = in_sizes[0] / (NTOK * DDIM);   // 8192
    const int smem_bytes = SMEM_FLOATS * sizeof(float);  // 76,608 B

    cudaFuncSetAttribute(SAM3E_kernel,
                         cudaFuncAttributeMaxDynamicSharedMemorySize, smem_bytes);

    SAM3E_kernel<<<B, 256, smem_bytes>>>(F, Kw, Qw, out);
}